// round 2
// baseline (speedup 1.0000x reference)
#include <cuda_runtime.h>
#include <math.h>

// ---------------- problem constants ----------------
#define BB   32
#define SS   576
#define FFE  700
#define DD   16
#define KCB  1024
#define MM   (BB*SS)      // 18432
#define E0   512
#define E1   256
#define E2   32           // 2*D
#define DEC0 1024
#define DEC1 512
#define NOUT (SS*FFE)     // 403200
#define ZFD  (SS*DD)      // 9216

// output layout in d_out (float32): [reconstructed | mean | log_var | vq_loss]
#define REC_OFF  0
#define MEAN_OFF (BB*NOUT)                 // 12902400
#define LV_OFF   (MEAN_OFF + MM*DD)        // 13197312
#define VQ_OFF   (LV_OFF + MM*DD)          // 13492224

#define NVQBLK   (MM/256)                  // 72

// ---------------- scratch (device globals, no allocs) ----------------
__device__ float g_h0[MM*E0];
__device__ float g_h1[MM*E1];
__device__ float g_enc[MM*E2];
__device__ float g_ze[MM*DD];
__device__ float g_zq[MM*DD];
__device__ float g_hd0[BB*DEC0];
__device__ float g_hd1[BB*DEC1];
__device__ float g_vqpart[NVQBLK];

// ---------------- tiled SGEMM: C = act(A[M,K] @ B[K,N] + bias) ----------------
template<int BM, int BN, int BK, int TM, int TN, int ACT>
__global__ void sgemm_kernel(const float* __restrict__ A,
                             const float* __restrict__ Bw,
                             const float* __restrict__ bias,
                             float* __restrict__ C,
                             int M, int N, int K)
{
    constexpr int TX = BN / TN;
    constexpr int TY = BM / TM;
    constexpr int NTH = TX * TY;
    constexpr int LDA = BM + 4;                 // pad kills STS bank conflicts
    __shared__ float As[BK * LDA];
    __shared__ float Bs[BK * BN];

    const int tid = threadIdx.x;
    const int tx = tid % TX;
    const int ty = tid / TX;
    const int row0 = blockIdx.y * BM;
    const int col0 = blockIdx.x * BN;

    float acc[TM][TN];
#pragma unroll
    for (int i = 0; i < TM; i++)
#pragma unroll
        for (int j = 0; j < TN; j++) acc[i][j] = 0.f;

    for (int k0 = 0; k0 < K; k0 += BK) {
        // A tile: BM x BK, stored transposed As[kk][m]
        for (int i = tid; i < BM * BK; i += NTH) {
            int m  = i / BK;
            int kk = i % BK;
            int kg = k0 + kk;
            As[kk * LDA + m] = (kg < K) ? A[(size_t)(row0 + m) * K + kg] : 0.f;
        }
        // B tile: BK x BN
        for (int i = tid; i < BK * BN; i += NTH) {
            int kk = i / BN;
            int n  = i % BN;
            int kg = k0 + kk;
            Bs[kk * BN + n] = (kg < K) ? Bw[(size_t)kg * N + col0 + n] : 0.f;
        }
        __syncthreads();

#pragma unroll
        for (int kk = 0; kk < BK; kk++) {
            float a[TM], b[TN];
#pragma unroll
            for (int i = 0; i < TM; i++) a[i] = As[kk * LDA + ty * TM + i];
#pragma unroll
            for (int j = 0; j < TN; j++) b[j] = Bs[kk * BN + tx * TN + j];
#pragma unroll
            for (int i = 0; i < TM; i++)
#pragma unroll
                for (int j = 0; j < TN; j++)
                    acc[i][j] = fmaf(a[i], b[j], acc[i][j]);
        }
        __syncthreads();
    }

#pragma unroll
    for (int i = 0; i < TM; i++) {
        int r = row0 + ty * TM + i;
#pragma unroll
        for (int j = 0; j < TN; j++) {
            int c = col0 + tx * TN + j;
            float v = acc[i][j] + bias[c];
            if (ACT) v = fmaxf(v, 0.f);
            C[(size_t)r * N + c] = v;
        }
    }
}

// ---------------- reparameterize + emit mean/log_var ----------------
__global__ void reparam_kernel(const float* __restrict__ enc,
                               const float* __restrict__ eps,
                               float* __restrict__ out_mean,
                               float* __restrict__ out_lv,
                               float* __restrict__ ze)
{
    int idx = blockIdx.x * 256 + threadIdx.x;
    if (idx >= MM * DD) return;
    int row = idx >> 4;
    int d   = idx & 15;
    float m  = enc[row * E2 + d];
    float lv = enc[row * E2 + DD + d];
    out_mean[idx] = m;
    out_lv[idx]   = lv;
    ze[idx] = fmaf(expf(0.5f * lv), eps[idx], m);
}

// ---------------- VQ: argmin over codebook + gather + loss partials ----------------
__global__ void vq_kernel(const float* __restrict__ ze,
                          const float* __restrict__ cb,
                          float* __restrict__ zq,
                          float* __restrict__ part)
{
    __shared__ float s_cb[256 * DD];
    __shared__ float s_csq[256];
    __shared__ float s_red[256];

    const int row = blockIdx.x * 256 + threadIdx.x;
    float z[DD];
#pragma unroll
    for (int d = 0; d < DD; d++) z[d] = ze[row * DD + d];

    float best = 3.4e38f;
    int bi = 0;
    for (int t = 0; t < KCB; t += 256) {
        __syncthreads();
        for (int i = threadIdx.x; i < 256 * DD; i += 256)
            s_cb[i] = cb[t * DD + i];
        __syncthreads();
        {
            float cs = 0.f;
#pragma unroll
            for (int d = 0; d < DD; d++) {
                float c = s_cb[threadIdx.x * DD + d];
                cs = fmaf(c, c, cs);
            }
            s_csq[threadIdx.x] = cs;
        }
        __syncthreads();
        for (int k = 0; k < 256; k++) {
            float dot = 0.f;
#pragma unroll
            for (int d = 0; d < DD; d++) dot = fmaf(z[d], s_cb[k * DD + d], dot);
            float score = s_csq[k] - 2.f * dot;   // z^2 term is row-constant
            if (score < best) { best = score; bi = t + k; }   // first-index ties
        }
    }

    float loss = 0.f;
#pragma unroll
    for (int d = 0; d < DD; d++) {
        float q = cb[bi * DD + d];
        zq[row * DD + d] = q;
        float df = z[d] - q;
        loss = fmaf(df, df, loss);
    }

    s_red[threadIdx.x] = loss;
    __syncthreads();
    for (int s = 128; s > 0; s >>= 1) {
        if (threadIdx.x < s) s_red[threadIdx.x] += s_red[threadIdx.x + s];
        __syncthreads();
    }
    if (threadIdx.x == 0) part[blockIdx.x] = s_red[0];
}

__global__ void vq_reduce_kernel(const float* __restrict__ part,
                                 float* __restrict__ out)
{
    if (threadIdx.x == 0) {
        float t = 0.f;
        for (int i = 0; i < NVQBLK; i++) t += part[i];
        out[0] = t / (float)(MM * DD);
    }
}

// ---------------- skinny-M GEMM (M=32), split-K with atomic accumulate ----------------
// C[32,N] += Z[32,K-chunk] @ W[K,N]-chunk.  One column per thread, 32 batch accs.
template<int KTILE>
__global__ void skinny_splitk_kernel(const float* __restrict__ Z,
                                     const float* __restrict__ W,
                                     float* __restrict__ C,
                                     int K, int N, int kchunk)
{
    const int j  = blockIdx.x * 128 + threadIdx.x;
    const int k0 = blockIdx.y * kchunk;
    const int kend = min(k0 + kchunk, K);
    __shared__ float s_z[BB * KTILE];

    float acc[BB];
#pragma unroll
    for (int b = 0; b < BB; b++) acc[b] = 0.f;

    for (int kt = k0; kt < kend; kt += KTILE) {
        __syncthreads();
        for (int i = threadIdx.x; i < BB * KTILE; i += 128) {
            int b  = i / KTILE;
            int kk = i % KTILE;
            s_z[i] = Z[(size_t)b * K + kt + kk];   // tiles always full by construction
        }
        __syncthreads();
        for (int kk = 0; kk < KTILE; kk += 4) {
            float w0 = W[(size_t)(kt + kk + 0) * N + j];
            float w1 = W[(size_t)(kt + kk + 1) * N + j];
            float w2 = W[(size_t)(kt + kk + 2) * N + j];
            float w3 = W[(size_t)(kt + kk + 3) * N + j];
#pragma unroll
            for (int b = 0; b < BB; b++) {
                float4 zz = *(const float4*)&s_z[b * KTILE + kk];  // broadcast LDS.128
                acc[b] = fmaf(zz.x, w0, acc[b]);
                acc[b] = fmaf(zz.y, w1, acc[b]);
                acc[b] = fmaf(zz.z, w2, acc[b]);
                acc[b] = fmaf(zz.w, w3, acc[b]);
            }
        }
    }
#pragma unroll
    for (int b = 0; b < BB; b++) atomicAdd(&C[b * N + j], acc[b]);
}

// ---------------- decoder final layer: fused bias + softplus, streams dw2 once ----------------
__global__ void skinny_d2_kernel(const float* __restrict__ Z,      // g_hd1 [32,512]
                                 const float* __restrict__ W,      // dw2 [512, 403200]
                                 const float* __restrict__ bias,   // db2 [403200]
                                 float* __restrict__ out)          // [32, 403200]
{
    constexpr int KTILE = 128;
    const int j = blockIdx.x * 128 + threadIdx.x;
    __shared__ float s_z[BB * KTILE];

    float acc[BB];
#pragma unroll
    for (int b = 0; b < BB; b++) acc[b] = 0.f;

    for (int kt = 0; kt < DEC1; kt += KTILE) {
        __syncthreads();
        for (int i = threadIdx.x; i < BB * KTILE; i += 128) {
            int b  = i / KTILE;
            int kk = i % KTILE;
            s_z[i] = Z[b * DEC1 + kt + kk];
        }
        __syncthreads();
        for (int kk = 0; kk < KTILE; kk += 4) {
            float w0 = W[(size_t)(kt + kk + 0) * NOUT + j];
            float w1 = W[(size_t)(kt + kk + 1) * NOUT + j];
            float w2 = W[(size_t)(kt + kk + 2) * NOUT + j];
            float w3 = W[(size_t)(kt + kk + 3) * NOUT + j];
#pragma unroll
            for (int b = 0; b < BB; b++) {
                float4 zz = *(const float4*)&s_z[b * KTILE + kk];
                acc[b] = fmaf(zz.x, w0, acc[b]);
                acc[b] = fmaf(zz.y, w1, acc[b]);
                acc[b] = fmaf(zz.z, w2, acc[b]);
                acc[b] = fmaf(zz.w, w3, acc[b]);
            }
        }
    }

    const float bv = bias[j];
#pragma unroll
    for (int b = 0; b < BB; b++) {
        float v = acc[b] + bv;
        float sp = (v > 20.f) ? v : log1pf(expf(v));   // softplus, stable
        out[(size_t)b * NOUT + j] = sp;
    }
}

// ---------------- small helpers ----------------
__global__ void zero_kernel(float* __restrict__ p, int n)
{
    int i = blockIdx.x * 256 + threadIdx.x;
    if (i < n) p[i] = 0.f;
}

__global__ void bias_relu_kernel(float* __restrict__ C,
                                 const float* __restrict__ bias,
                                 int N, int total)
{
    int i = blockIdx.x * 256 + threadIdx.x;
    if (i < total) {
        float v = C[i] + bias[i % N];
        C[i] = fmaxf(v, 0.f);
    }
}

// ---------------- launch ----------------
extern "C" void kernel_launch(void* const* d_in, const int* in_sizes, int n_in,
                              void* d_out, int out_size)
{
    const float* x    = (const float*)d_in[0];
    const float* eps  = (const float*)d_in[1];
    const float* ew0  = (const float*)d_in[2];
    const float* eb0  = (const float*)d_in[3];
    const float* ew1  = (const float*)d_in[4];
    const float* eb1  = (const float*)d_in[5];
    const float* ew2  = (const float*)d_in[6];
    const float* eb2  = (const float*)d_in[7];
    const float* dw0  = (const float*)d_in[8];
    const float* db0  = (const float*)d_in[9];
    const float* dw1  = (const float*)d_in[10];
    const float* db1  = (const float*)d_in[11];
    const float* dw2  = (const float*)d_in[12];
    const float* db2  = (const float*)d_in[13];
    const float* cb   = (const float*)d_in[14];
    float* out = (float*)d_out;

    // scratch pointers
    float *p_h0, *p_h1, *p_enc, *p_ze, *p_zq, *p_hd0, *p_hd1, *p_vq;
    cudaGetSymbolAddress((void**)&p_h0,  g_h0);
    cudaGetSymbolAddress((void**)&p_h1,  g_h1);
    cudaGetSymbolAddress((void**)&p_enc, g_enc);
    cudaGetSymbolAddress((void**)&p_ze,  g_ze);
    cudaGetSymbolAddress((void**)&p_zq,  g_zq);
    cudaGetSymbolAddress((void**)&p_hd0, g_hd0);
    cudaGetSymbolAddress((void**)&p_hd1, g_hd1);
    cudaGetSymbolAddress((void**)&p_vq,  g_vqpart);

    // encoder
    sgemm_kernel<128,64,16,8,4,1><<<dim3(E0/64, MM/128), 256>>>(x,    ew0, eb0, p_h0,  MM, E0, FFE);
    sgemm_kernel<128,64,16,8,4,1><<<dim3(E1/64, MM/128), 256>>>(p_h0, ew1, eb1, p_h1,  MM, E1, E0);
    sgemm_kernel<128,32,16,8,4,0><<<dim3(1,     MM/128), 128>>>(p_h1, ew2, eb2, p_enc, MM, E2, E1);

    // reparameterize (also writes mean / log_var outputs)
    reparam_kernel<<<(MM*DD + 255)/256, 256>>>(p_enc, eps, out + MEAN_OFF, out + LV_OFF, p_ze);

    // vector quantization + loss
    vq_kernel<<<NVQBLK, 256>>>(p_ze, cb, p_zq, p_vq);
    vq_reduce_kernel<<<1, 32>>>(p_vq, out + VQ_OFF);

    // decoder D0: [32,9216] @ [9216,1024], split-K=16 (chunks of 576 = 9 tiles of 64)
    zero_kernel<<<(BB*DEC0 + 255)/256, 256>>>(p_hd0, BB*DEC0);
    skinny_splitk_kernel<64><<<dim3(DEC0/128, 16), 128>>>(p_zq, dw0, p_hd0, ZFD, DEC0, 576);
    bias_relu_kernel<<<(BB*DEC0 + 255)/256, 256>>>(p_hd0, db0, DEC0, BB*DEC0);

    // decoder D1: [32,1024] @ [1024,512], split-K=8 (chunks of 128)
    zero_kernel<<<(BB*DEC1 + 255)/256, 256>>>(p_hd1, BB*DEC1);
    skinny_splitk_kernel<64><<<dim3(DEC1/128, 8), 128>>>(p_hd0, dw1, p_hd1, DEC0, DEC1, 128);
    bias_relu_kernel<<<(BB*DEC1 + 255)/256, 256>>>(p_hd1, db1, DEC1, BB*DEC1);

    // decoder D2: [32,512] @ [512,403200] + bias, softplus -> reconstructed
    skinny_d2_kernel<<<NOUT/128, 128>>>(p_hd1, dw2, db2, out + REC_OFF);
}

// round 4
// speedup vs baseline: 1.5928x; 1.5928x over previous
#include <cuda_runtime.h>
#include <math.h>

// ---------------- problem constants ----------------
#define BB   32
#define SS   576
#define FFE  700
#define DD   16
#define KCB  1024
#define MM   (BB*SS)      // 18432
#define E0   512
#define E1   256
#define E2   32           // 2*D
#define DEC0 1024
#define DEC1 512
#define NOUT (SS*FFE)     // 403200
#define ZFD  (SS*DD)      // 9216

// output layout in d_out (float32): [reconstructed | mean | log_var | vq_loss]
#define REC_OFF  0
#define MEAN_OFF (BB*NOUT)                 // 12902400
#define LV_OFF   (MEAN_OFF + MM*DD)        // 13197312
#define VQ_OFF   (LV_OFF + MM*DD)          // 13492224

#define NVQBLK   144                       // 144 blocks x 128 rows = 18432

typedef unsigned long long ull;

// ---------------- f32x2 packed-FMA helpers ----------------
__device__ __forceinline__ ull dup2(float x) {
    ull r;
    asm("mov.b64 %0, {%1, %1};" : "=l"(r) : "r"(__float_as_uint(x)));
    return r;
}
__device__ __forceinline__ void fma2(ull& d, ull a, ull b) {
    asm("fma.rn.f32x2 %0, %1, %2, %0;" : "+l"(d) : "l"(a), "l"(b));
}
__device__ __forceinline__ float2 unpk(ull v) {
    unsigned lo, hi;
    asm("mov.b64 {%0, %1}, %2;" : "=r"(lo), "=r"(hi) : "l"(v));
    return make_float2(__uint_as_float(lo), __uint_as_float(hi));
}

// ---------------- scratch (device globals, no allocs) ----------------
__device__ float g_h0[MM*E0];
__device__ float g_h1[MM*E1];
__device__ float g_enc[MM*E2];
__device__ float g_ze[MM*DD];
__device__ float g_zq[MM*DD];
__device__ float g_hd0[BB*DEC0];
__device__ float g_hd1[BB*DEC1];
__device__ float g_vqpart[NVQBLK];

// ============ f32x2 tiled SGEMM: C = act(A[M,K] @ B[K,N] + bias) ============
// BM=128, BN=128, BK=16, TM=8, TN=8, 256 threads. Requires M%128==0, N%128==0.
template<int ACT>
__global__ __launch_bounds__(256, 2)
void sgemm2_kernel(const float* __restrict__ A,
                   const float* __restrict__ Bw,
                   const float* __restrict__ bias,
                   float* __restrict__ C,
                   int M, int N, int K)
{
    constexpr int BM = 128, BN = 128, BK = 16;
    constexpr int LDA = BM + 4;                  // 132; 528B rows (16B aligned)
    __shared__ float As[BK * LDA];               // transposed: As[kk][m]
    __shared__ float Bs[BK * BN];

    const int tid  = threadIdx.x;
    const int tx   = tid & 15;                   // 0..15 -> 8 cols each
    const int ty   = tid >> 4;                   // 0..15 -> 8 rows each
    const int row0 = blockIdx.y * BM;
    const int col0 = blockIdx.x * BN;

    ull acc[8][4];
#pragma unroll
    for (int i = 0; i < 8; i++)
#pragma unroll
        for (int j = 0; j < 4; j++) acc[i][j] = 0ull;

    for (int k0 = 0; k0 < K; k0 += BK) {
        // ---- A tile: 128x16 floats, each thread 8 along K ----
        {
            int m  = tid >> 1;
            int kk = (tid & 1) * 8;
            int kg = k0 + kk;
            const float* ap = A + (size_t)(row0 + m) * K + kg;
            float v[8];
            if (kg + 7 < K) {
                float4 u0 = *(const float4*)(ap);
                float4 u1 = *(const float4*)(ap + 4);
                v[0]=u0.x; v[1]=u0.y; v[2]=u0.z; v[3]=u0.w;
                v[4]=u1.x; v[5]=u1.y; v[6]=u1.z; v[7]=u1.w;
            } else {
#pragma unroll
                for (int t = 0; t < 8; t++) v[t] = (kg + t < K) ? ap[t] : 0.f;
            }
#pragma unroll
            for (int t = 0; t < 8; t++) As[(kk + t) * LDA + m] = v[t];
        }
        // ---- B tile: 16x128 floats, each thread 8 along N ----
        {
            int kk = tid >> 4;
            int n  = (tid & 15) * 8;
            int kg = k0 + kk;
            float4 v0 = make_float4(0.f,0.f,0.f,0.f);
            float4 v1 = v0;
            if (kg < K) {
                const float* bp = Bw + (size_t)kg * N + col0 + n;
                v0 = *(const float4*)(bp);
                v1 = *(const float4*)(bp + 4);
            }
            *(float4*)&Bs[kk * BN + n]     = v0;
            *(float4*)&Bs[kk * BN + n + 4] = v1;
        }
        __syncthreads();

#pragma unroll
        for (int kk = 0; kk < BK; kk++) {
            longlong2 bl0 = *(const longlong2*)&Bs[kk * BN + tx * 8];
            longlong2 bl1 = *(const longlong2*)&Bs[kk * BN + tx * 8 + 4];
            ull bb[4] = { (ull)bl0.x, (ull)bl0.y, (ull)bl1.x, (ull)bl1.y };
            float4 a0 = *(const float4*)&As[kk * LDA + ty * 8];
            float4 a1 = *(const float4*)&As[kk * LDA + ty * 8 + 4];
            float av[8] = { a0.x, a0.y, a0.z, a0.w, a1.x, a1.y, a1.z, a1.w };
#pragma unroll
            for (int i = 0; i < 8; i++) {
                ull ad = dup2(av[i]);
#pragma unroll
                for (int j = 0; j < 4; j++) fma2(acc[i][j], ad, bb[j]);
            }
        }
        __syncthreads();
    }

    // ---- epilogue: bias (+relu), vectorized store ----
#pragma unroll
    for (int i = 0; i < 8; i++) {
        int r = row0 + ty * 8 + i;
        int c = col0 + tx * 8;
        float o[8];
#pragma unroll
        for (int j = 0; j < 4; j++) {
            float2 f = unpk(acc[i][j]);
            o[2*j]   = f.x;
            o[2*j+1] = f.y;
        }
#pragma unroll
        for (int j = 0; j < 8; j++) {
            float v = o[j] + bias[c + j];
            o[j] = ACT ? fmaxf(v, 0.f) : v;
        }
        *(float4*)&C[(size_t)r * N + c]     = make_float4(o[0],o[1],o[2],o[3]);
        *(float4*)&C[(size_t)r * N + c + 4] = make_float4(o[4],o[5],o[6],o[7]);
    }
}

// ---------------- scalar tiled SGEMM (kept for narrow N=32 layer) ----------------
template<int BM, int BN, int BK, int TM, int TN, int ACT>
__global__ void sgemm_kernel(const float* __restrict__ A,
                             const float* __restrict__ Bw,
                             const float* __restrict__ bias,
                             float* __restrict__ C,
                             int M, int N, int K)
{
    constexpr int TX = BN / TN;
    constexpr int TY = BM / TM;
    constexpr int NTH = TX * TY;
    constexpr int LDA = BM + 4;
    __shared__ float As[BK * LDA];
    __shared__ float Bs[BK * BN];

    const int tid = threadIdx.x;
    const int tx = tid % TX;
    const int ty = tid / TX;
    const int row0 = blockIdx.y * BM;
    const int col0 = blockIdx.x * BN;

    float acc[TM][TN];
#pragma unroll
    for (int i = 0; i < TM; i++)
#pragma unroll
        for (int j = 0; j < TN; j++) acc[i][j] = 0.f;

    for (int k0 = 0; k0 < K; k0 += BK) {
        for (int i = tid; i < BM * BK; i += NTH) {
            int m  = i / BK;
            int kk = i % BK;
            int kg = k0 + kk;
            As[kk * LDA + m] = (kg < K) ? A[(size_t)(row0 + m) * K + kg] : 0.f;
        }
        for (int i = tid; i < BK * BN; i += NTH) {
            int kk = i / BN;
            int n  = i % BN;
            int kg = k0 + kk;
            Bs[kk * BN + n] = (kg < K) ? Bw[(size_t)kg * N + col0 + n] : 0.f;
        }
        __syncthreads();

#pragma unroll
        for (int kk = 0; kk < BK; kk++) {
            float a[TM], b[TN];
#pragma unroll
            for (int i = 0; i < TM; i++) a[i] = As[kk * LDA + ty * TM + i];
#pragma unroll
            for (int j = 0; j < TN; j++) b[j] = Bs[kk * BN + tx * TN + j];
#pragma unroll
            for (int i = 0; i < TM; i++)
#pragma unroll
                for (int j = 0; j < TN; j++)
                    acc[i][j] = fmaf(a[i], b[j], acc[i][j]);
        }
        __syncthreads();
    }

#pragma unroll
    for (int i = 0; i < TM; i++) {
        int r = row0 + ty * TM + i;
#pragma unroll
        for (int j = 0; j < TN; j++) {
            int c = col0 + tx * TN + j;
            float v = acc[i][j] + bias[c];
            if (ACT) v = fmaxf(v, 0.f);
            C[(size_t)r * N + c] = v;
        }
    }
}

// ---------------- reparameterize + emit mean/log_var ----------------
__global__ void reparam_kernel(const float* __restrict__ enc,
                               const float* __restrict__ eps,
                               float* __restrict__ out_mean,
                               float* __restrict__ out_lv,
                               float* __restrict__ ze)
{
    int idx = blockIdx.x * 256 + threadIdx.x;
    if (idx >= MM * DD) return;
    int row = idx >> 4;
    int d   = idx & 15;
    float m  = enc[row * E2 + d];
    float lv = enc[row * E2 + DD + d];
    out_mean[idx] = m;
    out_lv[idx]   = lv;
    ze[idx] = fmaf(expf(0.5f * lv), eps[idx], m);
}

// ---------------- VQ: argmin over codebook + gather + loss partials ----------------
// 144 blocks x 128 threads -> one row per thread, full SM coverage.
__global__ void vq_kernel(const float* __restrict__ ze,
                          const float* __restrict__ cb,
                          float* __restrict__ zq,
                          float* __restrict__ part)
{
    __shared__ float s_cb[256 * DD];
    __shared__ float s_csq[256];
    __shared__ float s_red[128];

    const int row = blockIdx.x * 128 + threadIdx.x;
    float z[DD];
#pragma unroll
    for (int d = 0; d < DD; d++) z[d] = ze[row * DD + d];

    float best = 3.4e38f;
    int bi = 0;
    for (int t = 0; t < KCB; t += 256) {
        __syncthreads();
        for (int i = threadIdx.x; i < 256 * DD; i += 128)
            s_cb[i] = cb[t * DD + i];
        __syncthreads();
        for (int kc = threadIdx.x; kc < 256; kc += 128) {
            float cs = 0.f;
#pragma unroll
            for (int d = 0; d < DD; d++) {
                float c = s_cb[kc * DD + d];
                cs = fmaf(c, c, cs);
            }
            s_csq[kc] = cs;
        }
        __syncthreads();
#pragma unroll 2
        for (int k = 0; k < 256; k++) {
            float dot = 0.f;
#pragma unroll
            for (int d = 0; d < DD; d++) dot = fmaf(z[d], s_cb[k * DD + d], dot);
            float score = s_csq[k] - 2.f * dot;   // z^2 term is row-constant
            if (score < best) { best = score; bi = t + k; }   // first-index ties
        }
    }

    float loss = 0.f;
#pragma unroll
    for (int d = 0; d < DD; d++) {
        float q = cb[bi * DD + d];
        zq[row * DD + d] = q;
        float df = z[d] - q;
        loss = fmaf(df, df, loss);
    }

    s_red[threadIdx.x] = loss;
    __syncthreads();
    for (int s = 64; s > 0; s >>= 1) {
        if (threadIdx.x < s) s_red[threadIdx.x] += s_red[threadIdx.x + s];
        __syncthreads();
    }
    if (threadIdx.x == 0) part[blockIdx.x] = s_red[0];
}

__global__ void vq_reduce_kernel(const float* __restrict__ part,
                                 float* __restrict__ out)
{
    if (threadIdx.x == 0) {
        float t = 0.f;
        for (int i = 0; i < NVQBLK; i++) t += part[i];
        out[0] = t / (float)(MM * DD);
    }
}

// ---------------- skinny-M GEMM (M=32), split-K with atomic accumulate ----------------
template<int KTILE>
__global__ void skinny_splitk_kernel(const float* __restrict__ Z,
                                     const float* __restrict__ W,
                                     float* __restrict__ C,
                                     int K, int N, int kchunk)
{
    const int j  = blockIdx.x * 128 + threadIdx.x;
    const int k0 = blockIdx.y * kchunk;
    const int kend = min(k0 + kchunk, K);
    __shared__ float s_z[BB * KTILE];

    float acc[BB];
#pragma unroll
    for (int b = 0; b < BB; b++) acc[b] = 0.f;

    for (int kt = k0; kt < kend; kt += KTILE) {
        __syncthreads();
        for (int i = threadIdx.x; i < BB * KTILE; i += 128) {
            int b  = i / KTILE;
            int kk = i % KTILE;
            s_z[i] = Z[(size_t)b * K + kt + kk];
        }
        __syncthreads();
        for (int kk = 0; kk < KTILE; kk += 4) {
            float w0 = W[(size_t)(kt + kk + 0) * N + j];
            float w1 = W[(size_t)(kt + kk + 1) * N + j];
            float w2 = W[(size_t)(kt + kk + 2) * N + j];
            float w3 = W[(size_t)(kt + kk + 3) * N + j];
#pragma unroll
            for (int b = 0; b < BB; b++) {
                float4 zz = *(const float4*)&s_z[b * KTILE + kk];
                acc[b] = fmaf(zz.x, w0, acc[b]);
                acc[b] = fmaf(zz.y, w1, acc[b]);
                acc[b] = fmaf(zz.z, w2, acc[b]);
                acc[b] = fmaf(zz.w, w3, acc[b]);
            }
        }
    }
#pragma unroll
    for (int b = 0; b < BB; b++) atomicAdd(&C[b * N + j], acc[b]);
}

// ============ decoder final layer (f32x2): bias + softplus, streams dw2 once ============
// s_z transposed [kk][b] with pad-to-36 rows (16B-aligned, conflict-light).
// Accumulators pair adjacent batches; weight dup'd once per kk.
__global__ __launch_bounds__(128, 5)
void skinny_d2_kernel(const float* __restrict__ Z,      // g_hd1 [32,512]
                      const float* __restrict__ W,      // dw2 [512, 403200]
                      const float* __restrict__ bias,   // db2 [403200]
                      float* __restrict__ out)          // [32, 403200]
{
    constexpr int KT = 128;
    constexpr int LDZ = BB + 4;                 // 36 floats = 144B rows (16B aligned)
    __shared__ float s_z[KT * LDZ];

    const int j = blockIdx.x * 128 + threadIdx.x;

    ull acc[16];
#pragma unroll
    for (int q = 0; q < 16; q++) acc[q] = 0ull;

    for (int kt = 0; kt < DEC1; kt += KT) {
        __syncthreads();
        for (int i = threadIdx.x; i < BB * KT; i += 128) {
            int b  = i >> 7;        // i / 128
            int kk = i & 127;
            s_z[kk * LDZ + b] = Z[b * DEC1 + kt + kk];
        }
        __syncthreads();
#pragma unroll 4
        for (int kk = 0; kk < KT; kk++) {
            float w = W[(size_t)(kt + kk) * NOUT + j];
            ull w2 = dup2(w);
            const longlong2* zp = (const longlong2*)&s_z[kk * LDZ];
#pragma unroll
            for (int q = 0; q < 8; q++) {
                longlong2 t = zp[q];               // {b4q..4q+1, b4q+2..4q+3}
                fma2(acc[2*q],     w2, (ull)t.x);
                fma2(acc[2*q + 1], w2, (ull)t.y);
            }
        }
    }

    const float bv = bias[j];
#pragma unroll
    for (int q = 0; q < 16; q++) {
        float2 f = unpk(acc[q]);
        float v0 = f.x + bv;
        float v1 = f.y + bv;
        float s0 = (v0 > 20.f) ? v0 : log1pf(expf(v0));
        float s1 = (v1 > 20.f) ? v1 : log1pf(expf(v1));
        out[(size_t)(2*q)     * NOUT + j] = s0;
        out[(size_t)(2*q + 1) * NOUT + j] = s1;
    }
}

// ---------------- small helpers ----------------
__global__ void zero_kernel(float* __restrict__ p, int n)
{
    int i = blockIdx.x * 256 + threadIdx.x;
    if (i < n) p[i] = 0.f;
}

__global__ void bias_relu_kernel(float* __restrict__ C,
                                 const float* __restrict__ bias,
                                 int N, int total)
{
    int i = blockIdx.x * 256 + threadIdx.x;
    if (i < total) {
        float v = C[i] + bias[i % N];
        C[i] = fmaxf(v, 0.f);
    }
}

// ---------------- launch ----------------
extern "C" void kernel_launch(void* const* d_in, const int* in_sizes, int n_in,
                              void* d_out, int out_size)
{
    const float* x    = (const float*)d_in[0];
    const float* eps  = (const float*)d_in[1];
    const float* ew0  = (const float*)d_in[2];
    const float* eb0  = (const float*)d_in[3];
    const float* ew1  = (const float*)d_in[4];
    const float* eb1  = (const float*)d_in[5];
    const float* ew2  = (const float*)d_in[6];
    const float* eb2  = (const float*)d_in[7];
    const float* dw0  = (const float*)d_in[8];
    const float* db0  = (const float*)d_in[9];
    const float* dw1  = (const float*)d_in[10];
    const float* db1  = (const float*)d_in[11];
    const float* dw2  = (const float*)d_in[12];
    const float* db2  = (const float*)d_in[13];
    const float* cb   = (const float*)d_in[14];
    float* out = (float*)d_out;

    float *p_h0, *p_h1, *p_enc, *p_ze, *p_zq, *p_hd0, *p_hd1, *p_vq;
    cudaGetSymbolAddress((void**)&p_h0,  g_h0);
    cudaGetSymbolAddress((void**)&p_h1,  g_h1);
    cudaGetSymbolAddress((void**)&p_enc, g_enc);
    cudaGetSymbolAddress((void**)&p_ze,  g_ze);
    cudaGetSymbolAddress((void**)&p_zq,  g_zq);
    cudaGetSymbolAddress((void**)&p_hd0, g_hd0);
    cudaGetSymbolAddress((void**)&p_hd1, g_hd1);
    cudaGetSymbolAddress((void**)&p_vq,  g_vqpart);

    // encoder (f32x2 GEMMs for the two wide layers)
    sgemm2_kernel<1><<<dim3(E0/128, MM/128), 256>>>(x,    ew0, eb0, p_h0, MM, E0, FFE);
    sgemm2_kernel<1><<<dim3(E1/128, MM/128), 256>>>(p_h0, ew1, eb1, p_h1, MM, E1, E0);
    sgemm_kernel<128,32,16,8,4,0><<<dim3(1, MM/128), 128>>>(p_h1, ew2, eb2, p_enc, MM, E2, E1);

    // reparameterize (also writes mean / log_var outputs)
    reparam_kernel<<<(MM*DD + 255)/256, 256>>>(p_enc, eps, out + MEAN_OFF, out + LV_OFF, p_ze);

    // vector quantization + loss
    vq_kernel<<<NVQBLK, 128>>>(p_ze, cb, p_zq, p_vq);
    vq_reduce_kernel<<<1, 32>>>(p_vq, out + VQ_OFF);

    // decoder D0: [32,9216] @ [9216,1024], split-K=16
    zero_kernel<<<(BB*DEC0 + 255)/256, 256>>>(p_hd0, BB*DEC0);
    skinny_splitk_kernel<64><<<dim3(DEC0/128, 16), 128>>>(p_zq, dw0, p_hd0, ZFD, DEC0, 576);
    bias_relu_kernel<<<(BB*DEC0 + 255)/256, 256>>>(p_hd0, db0, DEC0, BB*DEC0);

    // decoder D1: [32,1024] @ [1024,512], split-K=8
    zero_kernel<<<(BB*DEC1 + 255)/256, 256>>>(p_hd1, BB*DEC1);
    skinny_splitk_kernel<64><<<dim3(DEC1/128, 8), 128>>>(p_hd0, dw1, p_hd1, DEC0, DEC1, 128);
    bias_relu_kernel<<<(BB*DEC1 + 255)/256, 256>>>(p_hd1, db1, DEC1, BB*DEC1);

    // decoder D2: [32,512] @ [512,403200] + bias, softplus -> reconstructed
    skinny_d2_kernel<<<NOUT/128, 128>>>(p_hd1, dw2, db2, out + REC_OFF);
}

// round 5
// speedup vs baseline: 1.5949x; 1.0013x over previous
#include <cuda_runtime.h>
#include <math.h>

// ---------------- problem constants ----------------
#define BB   32
#define SS   576
#define FFE  700
#define DD   16
#define KCB  1024
#define MM   (BB*SS)      // 18432
#define E0   512
#define E1   256
#define E2   32           // 2*D
#define DEC0 1024
#define DEC1 512
#define NOUT (SS*FFE)     // 403200
#define ZFD  (SS*DD)      // 9216

// output layout in d_out (float32): [reconstructed | mean | log_var | vq_loss]
#define REC_OFF  0
#define MEAN_OFF (BB*NOUT)                 // 12902400
#define LV_OFF   (MEAN_OFF + MM*DD)        // 13197312
#define VQ_OFF   (LV_OFF + MM*DD)          // 13492224

#define NVQBLK   144                       // 144 blocks x 128 rows = 18432

typedef unsigned long long ull;

// ---------------- f32x2 packed-FMA helpers ----------------
__device__ __forceinline__ ull dup2(float x) {
    ull r;
    asm("mov.b64 %0, {%1, %1};" : "=l"(r) : "r"(__float_as_uint(x)));
    return r;
}
__device__ __forceinline__ void fma2(ull& d, ull a, ull b) {
    asm("fma.rn.f32x2 %0, %1, %2, %0;" : "+l"(d) : "l"(a), "l"(b));
}
__device__ __forceinline__ float2 unpk(ull v) {
    unsigned lo, hi;
    asm("mov.b64 {%0, %1}, %2;" : "=r"(lo), "=r"(hi) : "l"(v));
    return make_float2(__uint_as_float(lo), __uint_as_float(hi));
}

// ---------------- scratch (device globals, no allocs) ----------------
__device__ float g_h0[MM*E0];
__device__ float g_h1[MM*E1];
__device__ float g_enc[MM*E2];
__device__ float g_ze[MM*DD];
__device__ float g_zq[MM*DD];
__device__ float g_hd0[BB*DEC0];
__device__ float g_hd1[BB*DEC1];
__device__ float g_vqpart[NVQBLK];

// ============ f32x2 tiled SGEMM: C = act(A[M,K] @ B[K,N] + bias) ============
// BM=128, BN=128, BK=16, TM=8, TN=8, 256 threads. Requires M%128==0, N%128==0.
template<int ACT>
__global__ __launch_bounds__(256, 2)
void sgemm2_kernel(const float* __restrict__ A,
                   const float* __restrict__ Bw,
                   const float* __restrict__ bias,
                   float* __restrict__ C,
                   int M, int N, int K)
{
    constexpr int BM = 128, BN = 128, BK = 16;
    constexpr int LDA = BM + 4;                  // 132; 528B rows (16B aligned)
    __shared__ float As[BK * LDA];               // transposed: As[kk][m]
    __shared__ float Bs[BK * BN];

    const int tid  = threadIdx.x;
    const int tx   = tid & 15;                   // 0..15 -> 8 cols each
    const int ty   = tid >> 4;                   // 0..15 -> 8 rows each
    const int row0 = blockIdx.y * BM;
    const int col0 = blockIdx.x * BN;

    ull acc[8][4];
#pragma unroll
    for (int i = 0; i < 8; i++)
#pragma unroll
        for (int j = 0; j < 4; j++) acc[i][j] = 0ull;

    for (int k0 = 0; k0 < K; k0 += BK) {
        // ---- A tile: 128x16 floats, each thread 8 along K ----
        {
            int m  = tid >> 1;
            int kk = (tid & 1) * 8;
            int kg = k0 + kk;
            const float* ap = A + (size_t)(row0 + m) * K + kg;
            float v[8];
            if (kg + 7 < K) {
                float4 u0 = *(const float4*)(ap);
                float4 u1 = *(const float4*)(ap + 4);
                v[0]=u0.x; v[1]=u0.y; v[2]=u0.z; v[3]=u0.w;
                v[4]=u1.x; v[5]=u1.y; v[6]=u1.z; v[7]=u1.w;
            } else {
#pragma unroll
                for (int t = 0; t < 8; t++) v[t] = (kg + t < K) ? ap[t] : 0.f;
            }
#pragma unroll
            for (int t = 0; t < 8; t++) As[(kk + t) * LDA + m] = v[t];
        }
        // ---- B tile: 16x128 floats, each thread 8 along N ----
        {
            int kk = tid >> 4;
            int n  = (tid & 15) * 8;
            int kg = k0 + kk;
            float4 v0 = make_float4(0.f,0.f,0.f,0.f);
            float4 v1 = v0;
            if (kg < K) {
                const float* bp = Bw + (size_t)kg * N + col0 + n;
                v0 = *(const float4*)(bp);
                v1 = *(const float4*)(bp + 4);
            }
            *(float4*)&Bs[kk * BN + n]     = v0;
            *(float4*)&Bs[kk * BN + n + 4] = v1;
        }
        __syncthreads();

#pragma unroll
        for (int kk = 0; kk < BK; kk++) {
            longlong2 bl0 = *(const longlong2*)&Bs[kk * BN + tx * 8];
            longlong2 bl1 = *(const longlong2*)&Bs[kk * BN + tx * 8 + 4];
            ull bb[4] = { (ull)bl0.x, (ull)bl0.y, (ull)bl1.x, (ull)bl1.y };
            float4 a0 = *(const float4*)&As[kk * LDA + ty * 8];
            float4 a1 = *(const float4*)&As[kk * LDA + ty * 8 + 4];
            float av[8] = { a0.x, a0.y, a0.z, a0.w, a1.x, a1.y, a1.z, a1.w };
#pragma unroll
            for (int i = 0; i < 8; i++) {
                ull ad = dup2(av[i]);
#pragma unroll
                for (int j = 0; j < 4; j++) fma2(acc[i][j], ad, bb[j]);
            }
        }
        __syncthreads();
    }

    // ---- epilogue: bias (+relu), vectorized store ----
#pragma unroll
    for (int i = 0; i < 8; i++) {
        int r = row0 + ty * 8 + i;
        int c = col0 + tx * 8;
        float o[8];
#pragma unroll
        for (int j = 0; j < 4; j++) {
            float2 f = unpk(acc[i][j]);
            o[2*j]   = f.x;
            o[2*j+1] = f.y;
        }
#pragma unroll
        for (int j = 0; j < 8; j++) {
            float v = o[j] + bias[c + j];
            o[j] = ACT ? fmaxf(v, 0.f) : v;
        }
        *(float4*)&C[(size_t)r * N + c]     = make_float4(o[0],o[1],o[2],o[3]);
        *(float4*)&C[(size_t)r * N + c + 4] = make_float4(o[4],o[5],o[6],o[7]);
    }
}

// ---------------- scalar tiled SGEMM (kept for narrow N=32 layer) ----------------
template<int BM, int BN, int BK, int TM, int TN, int ACT>
__global__ void sgemm_kernel(const float* __restrict__ A,
                             const float* __restrict__ Bw,
                             const float* __restrict__ bias,
                             float* __restrict__ C,
                             int M, int N, int K)
{
    constexpr int TX = BN / TN;
    constexpr int TY = BM / TM;
    constexpr int NTH = TX * TY;
    constexpr int LDA = BM + 4;
    __shared__ float As[BK * LDA];
    __shared__ float Bs[BK * BN];

    const int tid = threadIdx.x;
    const int tx = tid % TX;
    const int ty = tid / TX;
    const int row0 = blockIdx.y * BM;
    const int col0 = blockIdx.x * BN;

    float acc[TM][TN];
#pragma unroll
    for (int i = 0; i < TM; i++)
#pragma unroll
        for (int j = 0; j < TN; j++) acc[i][j] = 0.f;

    for (int k0 = 0; k0 < K; k0 += BK) {
        for (int i = tid; i < BM * BK; i += NTH) {
            int m  = i / BK;
            int kk = i % BK;
            int kg = k0 + kk;
            As[kk * LDA + m] = (kg < K) ? A[(size_t)(row0 + m) * K + kg] : 0.f;
        }
        for (int i = tid; i < BK * BN; i += NTH) {
            int kk = i / BN;
            int n  = i % BN;
            int kg = k0 + kk;
            Bs[kk * BN + n] = (kg < K) ? Bw[(size_t)kg * N + col0 + n] : 0.f;
        }
        __syncthreads();

#pragma unroll
        for (int kk = 0; kk < BK; kk++) {
            float a[TM], b[TN];
#pragma unroll
            for (int i = 0; i < TM; i++) a[i] = As[kk * LDA + ty * TM + i];
#pragma unroll
            for (int j = 0; j < TN; j++) b[j] = Bs[kk * BN + tx * TN + j];
#pragma unroll
            for (int i = 0; i < TM; i++)
#pragma unroll
                for (int j = 0; j < TN; j++)
                    acc[i][j] = fmaf(a[i], b[j], acc[i][j]);
        }
        __syncthreads();
    }

#pragma unroll
    for (int i = 0; i < TM; i++) {
        int r = row0 + ty * TM + i;
#pragma unroll
        for (int j = 0; j < TN; j++) {
            int c = col0 + tx * TN + j;
            float v = acc[i][j] + bias[c];
            if (ACT) v = fmaxf(v, 0.f);
            C[(size_t)r * N + c] = v;
        }
    }
}

// ---------------- reparameterize + emit mean/log_var ----------------
__global__ void reparam_kernel(const float* __restrict__ enc,
                               const float* __restrict__ eps,
                               float* __restrict__ out_mean,
                               float* __restrict__ out_lv,
                               float* __restrict__ ze)
{
    int idx = blockIdx.x * 256 + threadIdx.x;
    if (idx >= MM * DD) return;
    int row = idx >> 4;
    int d   = idx & 15;
    float m  = enc[row * E2 + d];
    float lv = enc[row * E2 + DD + d];
    out_mean[idx] = m;
    out_lv[idx]   = lv;
    ze[idx] = fmaf(expf(0.5f * lv), eps[idx], m);
}

// ---------------- VQ: argmin over codebook + gather + loss partials ----------------
// 144 blocks x 128 threads -> one row per thread, full SM coverage.
__global__ void vq_kernel(const float* __restrict__ ze,
                          const float* __restrict__ cb,
                          float* __restrict__ zq,
                          float* __restrict__ part)
{
    __shared__ float s_cb[256 * DD];
    __shared__ float s_csq[256];
    __shared__ float s_red[128];

    const int row = blockIdx.x * 128 + threadIdx.x;
    float z[DD];
#pragma unroll
    for (int d = 0; d < DD; d++) z[d] = ze[row * DD + d];

    float best = 3.4e38f;
    int bi = 0;
    for (int t = 0; t < KCB; t += 256) {
        __syncthreads();
        for (int i = threadIdx.x; i < 256 * DD; i += 128)
            s_cb[i] = cb[t * DD + i];
        __syncthreads();
        for (int kc = threadIdx.x; kc < 256; kc += 128) {
            float cs = 0.f;
#pragma unroll
            for (int d = 0; d < DD; d++) {
                float c = s_cb[kc * DD + d];
                cs = fmaf(c, c, cs);
            }
            s_csq[kc] = cs;
        }
        __syncthreads();
#pragma unroll 2
        for (int k = 0; k < 256; k++) {
            float dot = 0.f;
#pragma unroll
            for (int d = 0; d < DD; d++) dot = fmaf(z[d], s_cb[k * DD + d], dot);
            float score = s_csq[k] - 2.f * dot;   // z^2 term is row-constant
            if (score < best) { best = score; bi = t + k; }   // first-index ties
        }
    }

    float loss = 0.f;
#pragma unroll
    for (int d = 0; d < DD; d++) {
        float q = cb[bi * DD + d];
        zq[row * DD + d] = q;
        float df = z[d] - q;
        loss = fmaf(df, df, loss);
    }

    s_red[threadIdx.x] = loss;
    __syncthreads();
    for (int s = 64; s > 0; s >>= 1) {
        if (threadIdx.x < s) s_red[threadIdx.x] += s_red[threadIdx.x + s];
        __syncthreads();
    }
    if (threadIdx.x == 0) part[blockIdx.x] = s_red[0];
}

__global__ void vq_reduce_kernel(const float* __restrict__ part,
                                 float* __restrict__ out)
{
    if (threadIdx.x == 0) {
        float t = 0.f;
        for (int i = 0; i < NVQBLK; i++) t += part[i];
        out[0] = t / (float)(MM * DD);
    }
}

// ---------------- skinny-M GEMM (M=32), split-K with atomic accumulate ----------------
template<int KTILE>
__global__ void skinny_splitk_kernel(const float* __restrict__ Z,
                                     const float* __restrict__ W,
                                     float* __restrict__ C,
                                     int K, int N, int kchunk)
{
    const int j  = blockIdx.x * 128 + threadIdx.x;
    const int k0 = blockIdx.y * kchunk;
    const int kend = min(k0 + kchunk, K);
    __shared__ float s_z[BB * KTILE];

    float acc[BB];
#pragma unroll
    for (int b = 0; b < BB; b++) acc[b] = 0.f;

    for (int kt = k0; kt < kend; kt += KTILE) {
        __syncthreads();
        for (int i = threadIdx.x; i < BB * KTILE; i += 128) {
            int b  = i / KTILE;
            int kk = i % KTILE;
            s_z[i] = Z[(size_t)b * K + kt + kk];
        }
        __syncthreads();
        for (int kk = 0; kk < KTILE; kk += 4) {
            float w0 = W[(size_t)(kt + kk + 0) * N + j];
            float w1 = W[(size_t)(kt + kk + 1) * N + j];
            float w2 = W[(size_t)(kt + kk + 2) * N + j];
            float w3 = W[(size_t)(kt + kk + 3) * N + j];
#pragma unroll
            for (int b = 0; b < BB; b++) {
                float4 zz = *(const float4*)&s_z[b * KTILE + kk];
                acc[b] = fmaf(zz.x, w0, acc[b]);
                acc[b] = fmaf(zz.y, w1, acc[b]);
                acc[b] = fmaf(zz.z, w2, acc[b]);
                acc[b] = fmaf(zz.w, w3, acc[b]);
            }
        }
    }
#pragma unroll
    for (int b = 0; b < BB; b++) atomicAdd(&C[b * N + j], acc[b]);
}

// ============ decoder final layer (f32x2): bias + softplus, streams dw2 once ============
// s_z transposed [kk][b] with pad-to-36 rows (16B-aligned, conflict-light).
// Accumulators pair adjacent batches; weight dup'd once per kk.
__global__ __launch_bounds__(128, 5)
void skinny_d2_kernel(const float* __restrict__ Z,      // g_hd1 [32,512]
                      const float* __restrict__ W,      // dw2 [512, 403200]
                      const float* __restrict__ bias,   // db2 [403200]
                      float* __restrict__ out)          // [32, 403200]
{
    constexpr int KT = 128;
    constexpr int LDZ = BB + 4;                 // 36 floats = 144B rows (16B aligned)
    __shared__ float s_z[KT * LDZ];

    const int j = blockIdx.x * 128 + threadIdx.x;

    ull acc[16];
#pragma unroll
    for (int q = 0; q < 16; q++) acc[q] = 0ull;

    for (int kt = 0; kt < DEC1; kt += KT) {
        __syncthreads();
        for (int i = threadIdx.x; i < BB * KT; i += 128) {
            int b  = i >> 7;        // i / 128
            int kk = i & 127;
            s_z[kk * LDZ + b] = Z[b * DEC1 + kt + kk];
        }
        __syncthreads();
#pragma unroll 4
        for (int kk = 0; kk < KT; kk++) {
            float w = W[(size_t)(kt + kk) * NOUT + j];
            ull w2 = dup2(w);
            const longlong2* zp = (const longlong2*)&s_z[kk * LDZ];
#pragma unroll
            for (int q = 0; q < 8; q++) {
                longlong2 t = zp[q];               // {b4q..4q+1, b4q+2..4q+3}
                fma2(acc[2*q],     w2, (ull)t.x);
                fma2(acc[2*q + 1], w2, (ull)t.y);
            }
        }
    }

    const float bv = bias[j];
#pragma unroll
    for (int q = 0; q < 16; q++) {
        float2 f = unpk(acc[q]);
        float v0 = f.x + bv;
        float v1 = f.y + bv;
        float s0 = (v0 > 20.f) ? v0 : log1pf(expf(v0));
        float s1 = (v1 > 20.f) ? v1 : log1pf(expf(v1));
        out[(size_t)(2*q)     * NOUT + j] = s0;
        out[(size_t)(2*q + 1) * NOUT + j] = s1;
    }
}

// ---------------- small helpers ----------------
__global__ void zero_kernel(float* __restrict__ p, int n)
{
    int i = blockIdx.x * 256 + threadIdx.x;
    if (i < n) p[i] = 0.f;
}

__global__ void bias_relu_kernel(float* __restrict__ C,
                                 const float* __restrict__ bias,
                                 int N, int total)
{
    int i = blockIdx.x * 256 + threadIdx.x;
    if (i < total) {
        float v = C[i] + bias[i % N];
        C[i] = fmaxf(v, 0.f);
    }
}

// ---------------- launch ----------------
extern "C" void kernel_launch(void* const* d_in, const int* in_sizes, int n_in,
                              void* d_out, int out_size)
{
    const float* x    = (const float*)d_in[0];
    const float* eps  = (const float*)d_in[1];
    const float* ew0  = (const float*)d_in[2];
    const float* eb0  = (const float*)d_in[3];
    const float* ew1  = (const float*)d_in[4];
    const float* eb1  = (const float*)d_in[5];
    const float* ew2  = (const float*)d_in[6];
    const float* eb2  = (const float*)d_in[7];
    const float* dw0  = (const float*)d_in[8];
    const float* db0  = (const float*)d_in[9];
    const float* dw1  = (const float*)d_in[10];
    const float* db1  = (const float*)d_in[11];
    const float* dw2  = (const float*)d_in[12];
    const float* db2  = (const float*)d_in[13];
    const float* cb   = (const float*)d_in[14];
    float* out = (float*)d_out;

    float *p_h0, *p_h1, *p_enc, *p_ze, *p_zq, *p_hd0, *p_hd1, *p_vq;
    cudaGetSymbolAddress((void**)&p_h0,  g_h0);
    cudaGetSymbolAddress((void**)&p_h1,  g_h1);
    cudaGetSymbolAddress((void**)&p_enc, g_enc);
    cudaGetSymbolAddress((void**)&p_ze,  g_ze);
    cudaGetSymbolAddress((void**)&p_zq,  g_zq);
    cudaGetSymbolAddress((void**)&p_hd0, g_hd0);
    cudaGetSymbolAddress((void**)&p_hd1, g_hd1);
    cudaGetSymbolAddress((void**)&p_vq,  g_vqpart);

    // encoder (f32x2 GEMMs for the two wide layers)
    sgemm2_kernel<1><<<dim3(E0/128, MM/128), 256>>>(x,    ew0, eb0, p_h0, MM, E0, FFE);
    sgemm2_kernel<1><<<dim3(E1/128, MM/128), 256>>>(p_h0, ew1, eb1, p_h1, MM, E1, E0);
    sgemm_kernel<128,32,16,8,4,0><<<dim3(1, MM/128), 128>>>(p_h1, ew2, eb2, p_enc, MM, E2, E1);

    // reparameterize (also writes mean / log_var outputs)
    reparam_kernel<<<(MM*DD + 255)/256, 256>>>(p_enc, eps, out + MEAN_OFF, out + LV_OFF, p_ze);

    // vector quantization + loss
    vq_kernel<<<NVQBLK, 128>>>(p_ze, cb, p_zq, p_vq);
    vq_reduce_kernel<<<1, 32>>>(p_vq, out + VQ_OFF);

    // decoder D0: [32,9216] @ [9216,1024], split-K=16
    zero_kernel<<<(BB*DEC0 + 255)/256, 256>>>(p_hd0, BB*DEC0);
    skinny_splitk_kernel<64><<<dim3(DEC0/128, 16), 128>>>(p_zq, dw0, p_hd0, ZFD, DEC0, 576);
    bias_relu_kernel<<<(BB*DEC0 + 255)/256, 256>>>(p_hd0, db0, DEC0, BB*DEC0);

    // decoder D1: [32,1024] @ [1024,512], split-K=8
    zero_kernel<<<(BB*DEC1 + 255)/256, 256>>>(p_hd1, BB*DEC1);
    skinny_splitk_kernel<64><<<dim3(DEC1/128, 8), 128>>>(p_hd0, dw1, p_hd1, DEC0, DEC1, 128);
    bias_relu_kernel<<<(BB*DEC1 + 255)/256, 256>>>(p_hd1, db1, DEC1, BB*DEC1);

    // decoder D2: [32,512] @ [512,403200] + bias, softplus -> reconstructed
    skinny_d2_kernel<<<NOUT/128, 128>>>(p_hd1, dw2, db2, out + REC_OFF);
}

// round 7
// speedup vs baseline: 2.5804x; 1.6179x over previous
#include <cuda_runtime.h>
#include <cuda_bf16.h>
#include <math.h>
#include <stdint.h>

#define BB   32
#define SS   576
#define FFE  700
#define DD   16
#define KCB  1024
#define MM   (BB*SS)
#define E0   512
#define E1   256
#define E2   32
#define DEC0 1024
#define DEC1 512
#define NOUT (SS*FFE)
#define ZFD  (SS*DD)

#define REC_OFF  0
#define MEAN_OFF (BB*NOUT)
#define LV_OFF   (MEAN_OFF + MM*DD)
#define VQ_OFF   (LV_OFF + MM*DD)
#define NVQBLK   144

__device__ float g_h0[MM*E0];
__device__ float g_h1[MM*E1];
__device__ float g_enc[MM*E2];
__device__ float g_ze[MM*DD];
__device__ float g_zq[MM*DD];
__device__ float g_hd0[BB*DEC0];
__device__ float g_hd1[BB*DEC1];
__device__ float g_vqpart[NVQBLK];

// ---------------- warp-MMA helpers (sm_80-level ISA, safe on sm_103) ----------------
__device__ __forceinline__ uint32_t smem_u32(const void* p) {
    uint32_t a;
    asm("{ .reg .u64 t; cvta.to.shared.u64 t, %1; cvt.u32.u64 %0, t; }" : "=r"(a) : "l"(p));
    return a;
}
__device__ __forceinline__ void ldsm4(uint32_t& r0, uint32_t& r1, uint32_t& r2, uint32_t& r3, uint32_t addr) {
    asm volatile("ldmatrix.sync.aligned.m8n8.x4.shared.b16 {%0,%1,%2,%3}, [%4];"
        : "=r"(r0), "=r"(r1), "=r"(r2), "=r"(r3) : "r"(addr));
}
__device__ __forceinline__ void mma_bf16(float* d, const uint32_t* a, uint32_t b0, uint32_t b1) {
    asm volatile("mma.sync.aligned.m16n8k16.row.col.f32.bf16.bf16.f32 "
        "{%0,%1,%2,%3}, {%4,%5,%6,%7}, {%8,%9}, {%0,%1,%2,%3};"
        : "+f"(d[0]), "+f"(d[1]), "+f"(d[2]), "+f"(d[3])
        : "r"(a[0]), "r"(a[1]), "r"(a[2]), "r"(a[3]), "r"(b0), "r"(b1));
}
__device__ __forceinline__ uint32_t pack_bf2(float a, float b) {
    __nv_bfloat162 t = __floats2bfloat162_rn(a, b);
    return *(uint32_t*)&t;
}
// 16 floats -> 8 hi words + 8 lo words (2 bf16 each)
__device__ __forceinline__ void cvt16(const float* v, uint32_t* h, uint32_t* l) {
#pragma unroll
    for (int t = 0; t < 8; t++) {
        float v0 = v[2*t], v1 = v[2*t+1];
        float h0 = __bfloat162float(__float2bfloat16(v0));
        float h1 = __bfloat162float(__float2bfloat16(v1));
        h[t] = pack_bf2(h0, h1);
        l[t] = pack_bf2(v0 - h0, v1 - h1);
    }
}

// ======== wide MMA GEMM: C[M,N] = act(A[M,KK] @ W[KK,N] + bias) ========
// BM=128, BN=128, BK=32; 8 warps (4x2), warp tile 32x64. ACT 1=relu.
template<int KK, int ACT>
__global__ __launch_bounds__(256, 1)
void mma_gemm128(const float* __restrict__ A, const float* __restrict__ W,
                 const float* __restrict__ bias, float* __restrict__ C, int N)
{
    constexpr int LDK = 40;
    __shared__ __align__(16) uint16_t s_ah[128*LDK];
    __shared__ __align__(16) uint16_t s_al[128*LDK];
    __shared__ __align__(16) uint16_t s_bh[128*LDK];
    __shared__ __align__(16) uint16_t s_bl[128*LDK];
    __shared__ float s_bias[128];

    const int tid = threadIdx.x;
    const int wid = tid >> 5, lane = tid & 31;
    const int wm = wid & 3, wn = wid >> 2;
    const int row0 = blockIdx.y * 128, col0 = blockIdx.x * 128;
    if (tid < 128) s_bias[tid] = bias[col0 + tid];

    const int g = lane >> 3, li = lane & 7;
    const int a_off = (wm*32 + (g&1)*8 + li) * LDK + (g>>1)*8;
    const int b_off = (wn*64 + (g>>1)*8 + li) * LDK + (g&1)*8;
    const uint32_t ah_b = smem_u32(s_ah), al_b = smem_u32(s_al);
    const uint32_t bh_b = smem_u32(s_bh), bl_b = smem_u32(s_bl);

    float acc[2][8][4];
#pragma unroll
    for (int i = 0; i < 2; i++)
#pragma unroll
        for (int j = 0; j < 8; j++)
#pragma unroll
            for (int q = 0; q < 4; q++) acc[i][j][q] = 0.f;

    const int am = tid >> 1, akq = (tid & 1) << 4;
    const int bn = tid & 127, bkq = (tid >> 7) << 4;
    const float* arow = A + (size_t)(row0 + am) * KK;
    const float* wcol = W + col0 + bn;

    for (int k0 = 0; k0 < KK; k0 += 32) {
        {   // A tile 128x32 -> hi/lo
            float v[16];
            int kg = k0 + akq;
            if (kg + 16 <= KK) {
#pragma unroll
                for (int q = 0; q < 4; q++) {
                    float4 u = *(const float4*)(arow + kg + q*4);
                    v[q*4]=u.x; v[q*4+1]=u.y; v[q*4+2]=u.z; v[q*4+3]=u.w;
                }
            } else {
#pragma unroll
                for (int t = 0; t < 16; t++) v[t] = (kg + t < KK) ? arow[kg + t] : 0.f;
            }
            uint32_t h[8], l[8];
            cvt16(v, h, l);
            int off = am*LDK + akq;
            *(uint4*)&s_ah[off]   = make_uint4(h[0],h[1],h[2],h[3]);
            *(uint4*)&s_ah[off+8] = make_uint4(h[4],h[5],h[6],h[7]);
            *(uint4*)&s_al[off]   = make_uint4(l[0],l[1],l[2],l[3]);
            *(uint4*)&s_al[off+8] = make_uint4(l[4],l[5],l[6],l[7]);
        }
        {   // B tile: W[k0..k0+32, col0..+128] -> s_b[n][k]
            float v[16];
#pragma unroll
            for (int t = 0; t < 16; t++) {
                int kg = k0 + bkq + t;
                v[t] = (kg < KK) ? wcol[(size_t)kg * N] : 0.f;
            }
            uint32_t h[8], l[8];
            cvt16(v, h, l);
            int off = bn*LDK + bkq;
            *(uint4*)&s_bh[off]   = make_uint4(h[0],h[1],h[2],h[3]);
            *(uint4*)&s_bh[off+8] = make_uint4(h[4],h[5],h[6],h[7]);
            *(uint4*)&s_bl[off]   = make_uint4(l[0],l[1],l[2],l[3]);
            *(uint4*)&s_bl[off+8] = make_uint4(l[4],l[5],l[6],l[7]);
        }
        __syncthreads();
#pragma unroll
        for (int s = 0; s < 2; s++) {
            const int kb = s * 16;
            uint32_t ah[2][4], al[2][4];
#pragma unroll
            for (int mt = 0; mt < 2; mt++) {
                uint32_t ao = (uint32_t)(a_off + mt*16*LDK + kb) * 2;
                ldsm4(ah[mt][0], ah[mt][1], ah[mt][2], ah[mt][3], ah_b + ao);
                ldsm4(al[mt][0], al[mt][1], al[mt][2], al[mt][3], al_b + ao);
            }
#pragma unroll
            for (int nt = 0; nt < 4; nt++) {
                uint32_t bo = (uint32_t)(b_off + nt*16*LDK + kb) * 2;
                uint32_t bh[4], bl[4];
                ldsm4(bh[0], bh[1], bh[2], bh[3], bh_b + bo);
                ldsm4(bl[0], bl[1], bl[2], bl[3], bl_b + bo);
#pragma unroll
                for (int mt = 0; mt < 2; mt++) {
#pragma unroll
                    for (int ns = 0; ns < 2; ns++) {
                        float* d = acc[mt][nt*2 + ns];
                        mma_bf16(d, ah[mt], bh[2*ns], bh[2*ns+1]);
                        mma_bf16(d, ah[mt], bl[2*ns], bl[2*ns+1]);
                        mma_bf16(d, al[mt], bh[2*ns], bh[2*ns+1]);
                    }
                }
            }
        }
        __syncthreads();
    }

    const int r_l = lane >> 2, c_l = 2 * (lane & 3);
#pragma unroll
    for (int mt = 0; mt < 2; mt++) {
#pragma unroll
        for (int n8 = 0; n8 < 8; n8++) {
            int cb = wn*64 + n8*8 + c_l;
            int col = col0 + cb;
            float b0 = s_bias[cb], b1 = s_bias[cb + 1];
            float* d = acc[mt][n8];
            int row = row0 + wm*32 + mt*16 + r_l;
            float v0 = d[0] + b0, v1 = d[1] + b1, v2 = d[2] + b0, v3 = d[3] + b1;
            if (ACT == 1) { v0=fmaxf(v0,0.f); v1=fmaxf(v1,0.f); v2=fmaxf(v2,0.f); v3=fmaxf(v3,0.f); }
            *(float2*)&C[(size_t)row * N + col]       = make_float2(v0, v1);
            *(float2*)&C[(size_t)(row+8) * N + col]   = make_float2(v2, v3);
        }
    }
}

// ======== skinny MMA GEMM for D2: out[32,NOUT] = softplus(A[32,512]@W + bias) ========
// BM=32, BN=256; 8 warps (1x8), warp tile 32x32.
__global__ __launch_bounds__(256, 1)
void mma_gemm_d2(const float* __restrict__ A, const float* __restrict__ W,
                 const float* __restrict__ bias, float* __restrict__ C)
{
    constexpr int LDK = 40;
    __shared__ __align__(16) uint16_t s_ah[32*LDK];
    __shared__ __align__(16) uint16_t s_al[32*LDK];
    __shared__ __align__(16) uint16_t s_bh[256*LDK];
    __shared__ __align__(16) uint16_t s_bl[256*LDK];
    __shared__ float s_bias[256];

    const int tid = threadIdx.x;
    const int wid = tid >> 5, lane = tid & 31;
    const int n0 = blockIdx.x * 256;
    s_bias[tid] = bias[n0 + tid];

    const int g = lane >> 3, li = lane & 7;
    const int a_off = ((g&1)*8 + li) * LDK + (g>>1)*8;
    const int b_off = (wid*32 + (g>>1)*8 + li) * LDK + (g&1)*8;
    const uint32_t ah_b = smem_u32(s_ah), al_b = smem_u32(s_al);
    const uint32_t bh_b = smem_u32(s_bh), bl_b = smem_u32(s_bl);

    float acc[2][4][4];
#pragma unroll
    for (int i = 0; i < 2; i++)
#pragma unroll
        for (int j = 0; j < 4; j++)
#pragma unroll
            for (int q = 0; q < 4; q++) acc[i][j][q] = 0.f;

    const int am = tid >> 3, akq = (tid & 7) << 2;
    const float* arow = A + am * DEC1 + akq;
    const float* wcol = W + n0 + tid;

    for (int k0 = 0; k0 < DEC1; k0 += 32) {
        {   // A tile 32x32: 4 floats per thread
            float4 u = *(const float4*)(arow + k0);
            float h0 = __bfloat162float(__float2bfloat16(u.x));
            float h1 = __bfloat162float(__float2bfloat16(u.y));
            float h2 = __bfloat162float(__float2bfloat16(u.z));
            float h3 = __bfloat162float(__float2bfloat16(u.w));
            int off = am*LDK + akq;
            *(uint2*)&s_ah[off] = make_uint2(pack_bf2(h0,h1), pack_bf2(h2,h3));
            *(uint2*)&s_al[off] = make_uint2(pack_bf2(u.x-h0, u.y-h1), pack_bf2(u.z-h2, u.w-h3));
        }
#pragma unroll
        for (int hh = 0; hh < 2; hh++) {   // B tile: 256n x 32k, two 16-k halves
            float v[16];
#pragma unroll
            for (int t = 0; t < 16; t++)
                v[t] = wcol[(size_t)(k0 + hh*16 + t) * NOUT];
            uint32_t h[8], l[8];
            cvt16(v, h, l);
            int off = tid*LDK + hh*16;
            *(uint4*)&s_bh[off]   = make_uint4(h[0],h[1],h[2],h[3]);
            *(uint4*)&s_bh[off+8] = make_uint4(h[4],h[5],h[6],h[7]);
            *(uint4*)&s_bl[off]   = make_uint4(l[0],l[1],l[2],l[3]);
            *(uint4*)&s_bl[off+8] = make_uint4(l[4],l[5],l[6],l[7]);
        }
        __syncthreads();
#pragma unroll
        for (int s = 0; s < 2; s++) {
            const int kb = s * 16;
            uint32_t ah[2][4], al[2][4];
#pragma unroll
            for (int mt = 0; mt < 2; mt++) {
                uint32_t ao = (uint32_t)(a_off + mt*16*LDK + kb) * 2;
                ldsm4(ah[mt][0], ah[mt][1], ah[mt][2], ah[mt][3], ah_b + ao);
                ldsm4(al[mt][0], al[mt][1], al[mt][2], al[mt][3], al_b + ao);
            }
#pragma unroll
            for (int nt = 0; nt < 2; nt++) {
                uint32_t bo = (uint32_t)(b_off + nt*16*LDK + kb) * 2;
                uint32_t bh[4], bl[4];
                ldsm4(bh[0], bh[1], bh[2], bh[3], bh_b + bo);
                ldsm4(bl[0], bl[1], bl[2], bl[3], bl_b + bo);
#pragma unroll
                for (int mt = 0; mt < 2; mt++) {
#pragma unroll
                    for (int ns = 0; ns < 2; ns++) {
                        float* d = acc[mt][nt*2 + ns];
                        mma_bf16(d, ah[mt], bh[2*ns], bh[2*ns+1]);
                        mma_bf16(d, ah[mt], bl[2*ns], bl[2*ns+1]);
                        mma_bf16(d, al[mt], bh[2*ns], bh[2*ns+1]);
                    }
                }
            }
        }
        __syncthreads();
    }

    const int r_l = lane >> 2, c_l = 2 * (lane & 3);
#pragma unroll
    for (int mt = 0; mt < 2; mt++) {
#pragma unroll
        for (int n8 = 0; n8 < 4; n8++) {
            int cb = wid*32 + n8*8 + c_l;
            int col = n0 + cb;
            float b0 = s_bias[cb], b1 = s_bias[cb + 1];
            float* d = acc[mt][n8];
            int row = mt*16 + r_l;
            float v[4] = { d[0]+b0, d[1]+b1, d[2]+b0, d[3]+b1 };
#pragma unroll
            for (int q = 0; q < 4; q++) v[q] = (v[q] > 20.f) ? v[q] : log1pf(expf(v[q]));
            *(float2*)&C[(size_t)row * NOUT + col]     = make_float2(v[0], v[1]);
            *(float2*)&C[(size_t)(row+8) * NOUT + col] = make_float2(v[2], v[3]);
        }
    }
}

// ---------- scalar SGEMM (encoder head, N=32) ----------
template<int BM, int BN, int BK, int TM, int TN, int ACT>
__global__ void sgemm_kernel(const float* __restrict__ A, const float* __restrict__ Bw,
                             const float* __restrict__ bias, float* __restrict__ C,
                             int M, int N, int K)
{
    constexpr int TX = BN / TN, TY = BM / TM, NTH = TX * TY, LDA = BM + 4;
    __shared__ float As[BK * LDA];
    __shared__ float Bs[BK * BN];
    const int tid = threadIdx.x, tx = tid % TX, ty = tid / TX;
    const int row0 = blockIdx.y * BM, col0 = blockIdx.x * BN;

    float acc[TM][TN];
#pragma unroll
    for (int i = 0; i < TM; i++)
#pragma unroll
        for (int j = 0; j < TN; j++) acc[i][j] = 0.f;

    for (int k0 = 0; k0 < K; k0 += BK) {
        for (int i = tid; i < BM * BK; i += NTH) {
            int m = i / BK, kk = i % BK, kg = k0 + kk;
            As[kk * LDA + m] = (kg < K) ? A[(size_t)(row0 + m) * K + kg] : 0.f;
        }
        for (int i = tid; i < BK * BN; i += NTH) {
            int kk = i / BN, n = i % BN, kg = k0 + kk;
            Bs[kk * BN + n] = (kg < K) ? Bw[(size_t)kg * N + col0 + n] : 0.f;
        }
        __syncthreads();
#pragma unroll
        for (int kk = 0; kk < BK; kk++) {
            float a[TM], b[TN];
#pragma unroll
            for (int i = 0; i < TM; i++) a[i] = As[kk * LDA + ty * TM + i];
#pragma unroll
            for (int j = 0; j < TN; j++) b[j] = Bs[kk * BN + tx * TN + j];
#pragma unroll
            for (int i = 0; i < TM; i++)
#pragma unroll
                for (int j = 0; j < TN; j++) acc[i][j] = fmaf(a[i], b[j], acc[i][j]);
        }
        __syncthreads();
    }
#pragma unroll
    for (int i = 0; i < TM; i++) {
        int r = row0 + ty * TM + i;
#pragma unroll
        for (int j = 0; j < TN; j++) {
            int c = col0 + tx * TN + j;
            float v = acc[i][j] + bias[c];
            if (ACT) v = fmaxf(v, 0.f);
            C[(size_t)r * N + c] = v;
        }
    }
}

__global__ void reparam_kernel(const float* __restrict__ enc, const float* __restrict__ eps,
                               float* __restrict__ om, float* __restrict__ olv,
                               float* __restrict__ ze)
{
    int idx = blockIdx.x * 256 + threadIdx.x;
    if (idx >= MM * DD) return;
    int row = idx >> 4, d = idx & 15;
    float m = enc[row * E2 + d], lv = enc[row * E2 + DD + d];
    om[idx] = m; olv[idx] = lv;
    ze[idx] = fmaf(expf(0.5f * lv), eps[idx], m);
}

__global__ void vq_kernel(const float* __restrict__ ze, const float* __restrict__ cb,
                          float* __restrict__ zq, float* __restrict__ part)
{
    __shared__ float s_cb[256 * DD];
    __shared__ float s_csq[256];
    __shared__ float s_red[128];
    const int row = blockIdx.x * 128 + threadIdx.x;
    float z[DD];
#pragma unroll
    for (int d = 0; d < DD; d++) z[d] = ze[row * DD + d];

    float best = 3.4e38f; int bi = 0;
    for (int t = 0; t < KCB; t += 256) {
        __syncthreads();
        for (int i = threadIdx.x; i < 256 * DD; i += 128) s_cb[i] = cb[t * DD + i];
        __syncthreads();
        for (int kc = threadIdx.x; kc < 256; kc += 128) {
            float cs = 0.f;
#pragma unroll
            for (int d = 0; d < DD; d++) { float c = s_cb[kc * DD + d]; cs = fmaf(c, c, cs); }
            s_csq[kc] = cs;
        }
        __syncthreads();
#pragma unroll 2
        for (int k = 0; k < 256; k++) {
            float dot = 0.f;
#pragma unroll
            for (int d = 0; d < DD; d++) dot = fmaf(z[d], s_cb[k * DD + d], dot);
            float score = s_csq[k] - 2.f * dot;
            if (score < best) { best = score; bi = t + k; }
        }
    }
    float loss = 0.f;
#pragma unroll
    for (int d = 0; d < DD; d++) {
        float q = cb[bi * DD + d];
        zq[row * DD + d] = q;
        float df = z[d] - q;
        loss = fmaf(df, df, loss);
    }
    s_red[threadIdx.x] = loss;
    __syncthreads();
    for (int s = 64; s > 0; s >>= 1) {
        if (threadIdx.x < s) s_red[threadIdx.x] += s_red[threadIdx.x + s];
        __syncthreads();
    }
    if (threadIdx.x == 0) part[blockIdx.x] = s_red[0];
}

__global__ void vq_reduce_kernel(const float* __restrict__ part, float* __restrict__ out)
{
    if (threadIdx.x == 0) {
        float t = 0.f;
        for (int i = 0; i < NVQBLK; i++) t += part[i];
        out[0] = t / (float)(MM * DD);
    }
}

template<int KTILE>
__global__ void skinny_splitk_kernel(const float* __restrict__ Z, const float* __restrict__ W,
                                     float* __restrict__ C, int K, int N, int kchunk)
{
    const int j = blockIdx.x * 128 + threadIdx.x;
    const int k0 = blockIdx.y * kchunk;
    const int kend = min(k0 + kchunk, K);
    __shared__ float s_z[BB * KTILE];
    float acc[BB];
#pragma unroll
    for (int b = 0; b < BB; b++) acc[b] = 0.f;
    for (int kt = k0; kt < kend; kt += KTILE) {
        __syncthreads();
        for (int i = threadIdx.x; i < BB * KTILE; i += 128) {
            int b = i / KTILE, kk = i % KTILE;
            s_z[i] = Z[(size_t)b * K + kt + kk];
        }
        __syncthreads();
        for (int kk = 0; kk < KTILE; kk += 4) {
            float w0 = W[(size_t)(kt + kk + 0) * N + j];
            float w1 = W[(size_t)(kt + kk + 1) * N + j];
            float w2 = W[(size_t)(kt + kk + 2) * N + j];
            float w3 = W[(size_t)(kt + kk + 3) * N + j];
#pragma unroll
            for (int b = 0; b < BB; b++) {
                float4 zz = *(const float4*)&s_z[b * KTILE + kk];
                acc[b] = fmaf(zz.x, w0, acc[b]);
                acc[b] = fmaf(zz.y, w1, acc[b]);
                acc[b] = fmaf(zz.z, w2, acc[b]);
                acc[b] = fmaf(zz.w, w3, acc[b]);
            }
        }
    }
#pragma unroll
    for (int b = 0; b < BB; b++) atomicAdd(&C[b * N + j], acc[b]);
}

__global__ void zero_kernel(float* __restrict__ p, int n)
{
    int i = blockIdx.x * 256 + threadIdx.x;
    if (i < n) p[i] = 0.f;
}
__global__ void bias_relu_kernel(float* __restrict__ C, const float* __restrict__ bias,
                                 int N, int total)
{
    int i = blockIdx.x * 256 + threadIdx.x;
    if (i < total) { float v = C[i] + bias[i % N]; C[i] = fmaxf(v, 0.f); }
}

extern "C" void kernel_launch(void* const* d_in, const int* in_sizes, int n_in,
                              void* d_out, int out_size)
{
    const float* x   = (const float*)d_in[0];
    const float* eps = (const float*)d_in[1];
    const float* ew0 = (const float*)d_in[2];
    const float* eb0 = (const float*)d_in[3];
    const float* ew1 = (const float*)d_in[4];
    const float* eb1 = (const float*)d_in[5];
    const float* ew2 = (const float*)d_in[6];
    const float* eb2 = (const float*)d_in[7];
    const float* dw0 = (const float*)d_in[8];
    const float* db0 = (const float*)d_in[9];
    const float* dw1 = (const float*)d_in[10];
    const float* db1 = (const float*)d_in[11];
    const float* dw2 = (const float*)d_in[12];
    const float* db2 = (const float*)d_in[13];
    const float* cb  = (const float*)d_in[14];
    float* out = (float*)d_out;

    float *p_h0, *p_h1, *p_enc, *p_ze, *p_zq, *p_hd0, *p_hd1, *p_vq;
    cudaGetSymbolAddress((void**)&p_h0,  g_h0);
    cudaGetSymbolAddress((void**)&p_h1,  g_h1);
    cudaGetSymbolAddress((void**)&p_enc, g_enc);
    cudaGetSymbolAddress((void**)&p_ze,  g_ze);
    cudaGetSymbolAddress((void**)&p_zq,  g_zq);
    cudaGetSymbolAddress((void**)&p_hd0, g_hd0);
    cudaGetSymbolAddress((void**)&p_hd1, g_hd1);
    cudaGetSymbolAddress((void**)&p_vq,  g_vqpart);

    // encoder L0: [18432,700]@[700,512] relu  (warp MMA, bf16 split)
    mma_gemm128<FFE, 1><<<dim3(E0/128, MM/128), 256>>>(x, ew0, eb0, p_h0, E0);
    // encoder L1: [18432,512]@[512,256] relu
    mma_gemm128<E0, 1><<<dim3(E1/128, MM/128), 256>>>(p_h0, ew1, eb1, p_h1, E1);
    // encoder head (N=32, scalar, exact fp32)
    sgemm_kernel<128,32,16,8,4,0><<<dim3(1, MM/128), 128>>>(p_h1, ew2, eb2, p_enc, MM, E2, E1);

    reparam_kernel<<<(MM*DD + 255)/256, 256>>>(p_enc, eps, out + MEAN_OFF, out + LV_OFF, p_ze);

    vq_kernel<<<NVQBLK, 128>>>(p_ze, cb, p_zq, p_vq);
    vq_reduce_kernel<<<1, 32>>>(p_vq, out + VQ_OFF);

    // decoder D0 / D1: skinny scalar split-K (exact fp32)
    zero_kernel<<<(BB*DEC0 + 255)/256, 256>>>(p_hd0, BB*DEC0);
    skinny_splitk_kernel<64><<<dim3(DEC0/128, 16), 128>>>(p_zq, dw0, p_hd0, ZFD, DEC0, 576);
    bias_relu_kernel<<<(BB*DEC0 + 255)/256, 256>>>(p_hd0, db0, DEC0, BB*DEC0);

    zero_kernel<<<(BB*DEC1 + 255)/256, 256>>>(p_hd1, BB*DEC1);
    skinny_splitk_kernel<64><<<dim3(DEC1/128, 8), 128>>>(p_hd0, dw1, p_hd1, DEC0, DEC1, 128);
    bias_relu_kernel<<<(BB*DEC1 + 255)/256, 256>>>(p_hd1, db1, DEC1, BB*DEC1);

    // decoder D2: [32,512]@[512,403200] + bias + softplus (skinny warp MMA)
    mma_gemm_d2<<<NOUT/256, 256>>>(p_hd1, dw2, db2, out + REC_OFF);
}